// round 3
// baseline (speedup 1.0000x reference)
#include <cuda_runtime.h>
#include <cstdint>

#define IND    160   // concat dim
#define EDD    32    // edge feature dim
#define NDD    64    // node feature dim
#define NLAYER 3
#define TILE   128   // edges per block
#define XROWF  132   // staged row length in floats (128 + 4 pad -> conflict-free LDS.128)
#define XROW4  33    // in float4

typedef unsigned long long u64;

// scratch for LayerNorm-folded weights (device globals: no allocation allowed)
__device__ float d_Wg[NLAYER * IND * EDD];  // g[k] * W1[k][c]
__device__ float d_S [NLAYER * EDD];        // sum_k g[k]*W1[k][c]
__device__ float d_T [NLAYER * EDD];        // sum_k b[k]*W1[k][c] + b1[c]

__device__ __forceinline__ u64 pack2(float lo, float hi) {
    u64 r; asm("mov.b64 %0,{%1,%2};" : "=l"(r) : "f"(lo), "f"(hi)); return r;
}
__device__ __forceinline__ void unpack2(u64 v, float& lo, float& hi) {
    asm("mov.b64 {%0,%1},%2;" : "=f"(lo), "=f"(hi) : "l"(v));
}
// packed dual fp32 FMA (sm_100+): d = a*b + c per 32-bit lane
__device__ __forceinline__ u64 ffma2(u64 a, u64 b, u64 c) {
    u64 d; asm("fma.rn.f32x2 %0,%1,%2,%3;" : "=l"(d) : "l"(a), "l"(b), "l"(c)); return d;
}

// Fold LayerNorm affine into the first GEMM:
// y1[c] = rs*( dot(x, Wg[:,c]) - mu*S[c] ) + T[c]
__global__ void prep_kernel(const float* __restrict__ ln_g, const float* __restrict__ ln_b,
                            const float* __restrict__ w1,   const float* __restrict__ b1) {
    int l = blockIdx.x;   // 0..2
    int c = threadIdx.x;  // 0..31
    float s = 0.f, t = 0.f;
    for (int k = 0; k < IND; k++) {
        float wv = w1[(l * IND + k) * EDD + c];
        float wg = ln_g[l * IND + k] * wv;
        d_Wg[(l * IND + k) * EDD + c] = wg;
        s += wg;
        t = fmaf(ln_b[l * IND + k], wv, t);
    }
    d_S[l * EDD + c] = s;
    d_T[l * EDD + c] = t + b1[l * EDD + c];
}

__global__ void __launch_bounds__(TILE, 2)
edge_kernel(const float* __restrict__ nf, const float* __restrict__ ew_g,
            const float* __restrict__ w2g, const float* __restrict__ b2g,
            const int* __restrict__ ei, const int* __restrict__ ej,
            float* __restrict__ out, int E)
{
    extern __shared__ float sm[];
    float* xs   = sm;                      // TILE*XROWF staged [nf_i | nf_j] per edge
    float* wg_s = xs + TILE * XROWF;       // IND*EDD
    float* w2_s = wg_s + IND * EDD;        // EDD*EDD
    float* S_s  = w2_s + EDD * EDD;        // EDD
    float* T_s  = S_s + EDD;               // EDD
    float* b2_s = T_s + EDD;               // EDD
    int*   ii_s = (int*)(b2_s + EDD);      // TILE
    int*   jj_s = ii_s + TILE;             // TILE

    const int tid = threadIdx.x;
    const long long e0 = (long long)blockIdx.x * TILE;
    const long long eg = e0 + tid;
    const bool valid = (eg < E);
    const long long egc = valid ? eg : 0;

    ii_s[tid] = ei[egc];
    jj_s[tid] = ej[egc];
    __syncthreads();

    // ---- gather endpoint node features into smem (warp-coalesced: 16 lanes per row) ----
    const float4* nf4 = (const float4*)nf;
    float4* xs4 = (float4*)xs;
    #pragma unroll
    for (int r = 0; r < 16; r++) {
        int f    = r * TILE + tid;  // 0..2047
        int e    = f >> 4;          // edge slot in block
        int comp = f & 15;          // float4 within 64-float row
        float4 vi = nf4[(long long)ii_s[e] * 16 + comp];
        float4 vj = nf4[(long long)jj_s[e] * 16 + comp];
        xs4[e * XROW4 + comp]      = vi;
        xs4[e * XROW4 + 16 + comp] = vj;
    }

    // ---- edge features live in registers across all 3 layers ----
    float ewv[EDD];
    {
        const float4* er = (const float4*)(ew_g + egc * EDD);
        #pragma unroll
        for (int t = 0; t < 8; t++) {
            float4 v = er[t];
            ewv[4*t] = v.x; ewv[4*t+1] = v.y; ewv[4*t+2] = v.z; ewv[4*t+3] = v.w;
        }
    }

    const float4* xr = (const float4*)xs + tid * XROW4;

    for (int l = 0; l < NLAYER; l++) {
        __syncthreads();  // covers staging (l==0) and prior-layer weight reads (l>0)
        for (int t = tid; t < IND * EDD; t += TILE) wg_s[t] = d_Wg[l * IND * EDD + t];
        for (int t = tid; t < EDD * EDD; t += TILE) w2_s[t] = w2g[l * EDD * EDD + t];
        if (tid < EDD) {
            S_s[tid]  = d_S[l * EDD + tid];
            T_s[tid]  = d_T[l * EDD + tid];
            b2_s[tid] = b2g[l * EDD + tid];
        }
        __syncthreads();

        // ---- GEMM1 fused with LN stats: one pass over x accumulates sum, sumsq, 32 dots ----
        u64 dot[16];
        #pragma unroll
        for (int t = 0; t < 16; t++) dot[t] = 0ull;
        float s = 0.f, q = 0.f;

        #pragma unroll 4
        for (int kq = 0; kq < 32; kq++) {          // node-feature part: k = 0..127
            float4 xv = xr[kq];
            float xk4[4] = {xv.x, xv.y, xv.z, xv.w};
            #pragma unroll
            for (int u = 0; u < 4; u++) {
                float xk = xk4[u];
                s += xk;
                q  = fmaf(xk, xk, q);
                u64 xx = pack2(xk, xk);
                const ulonglong2* wr = (const ulonglong2*)(wg_s + (kq * 4 + u) * EDD);
                #pragma unroll
                for (int t = 0; t < 8; t++) {
                    ulonglong2 wv = wr[t];
                    dot[2*t]   = ffma2(xx, wv.x, dot[2*t]);
                    dot[2*t+1] = ffma2(xx, wv.y, dot[2*t+1]);
                }
            }
        }
        #pragma unroll 4
        for (int ke = 0; ke < EDD; ke++) {         // edge-feature part: k = 128..159
            float xk = ewv[ke];
            s += xk;
            q  = fmaf(xk, xk, q);
            u64 xx = pack2(xk, xk);
            const ulonglong2* wr = (const ulonglong2*)(wg_s + (128 + ke) * EDD);
            #pragma unroll
            for (int t = 0; t < 8; t++) {
                ulonglong2 wv = wr[t];
                dot[2*t]   = ffma2(xx, wv.x, dot[2*t]);
                dot[2*t+1] = ffma2(xx, wv.y, dot[2*t+1]);
            }
        }

        float mu  = s * (1.f / IND);
        float var = q * (1.f / IND) - mu * mu;
        float rs  = rsqrtf(var + 1e-5f);

        // ---- finalize LN-folded linear, LeakyReLU ----
        float y1[EDD];
        #pragma unroll
        for (int t = 0; t < 16; t++) {
            float a, b; unpack2(dot[t], a, b);
            float c0 = fmaf(rs, a - mu * S_s[2*t],     T_s[2*t]);
            float c1 = fmaf(rs, b - mu * S_s[2*t + 1], T_s[2*t + 1]);
            y1[2*t]     = fmaxf(c0, 0.01f * c0);
            y1[2*t + 1] = fmaxf(c1, 0.01f * c1);
        }

        // ---- GEMM2 (32x32) + bias, packed f32x2 ----
        u64 acc[16];
        {
            const ulonglong2* b2p = (const ulonglong2*)b2_s;
            #pragma unroll
            for (int t = 0; t < 8; t++) { ulonglong2 v = b2p[t]; acc[2*t] = v.x; acc[2*t+1] = v.y; }
        }
        #pragma unroll 4
        for (int k2 = 0; k2 < EDD; k2++) {
            u64 yy = pack2(y1[k2], y1[k2]);
            const ulonglong2* wr = (const ulonglong2*)(w2_s + k2 * EDD);
            #pragma unroll
            for (int t = 0; t < 8; t++) {
                ulonglong2 wv = wr[t];
                acc[2*t]   = ffma2(yy, wv.x, acc[2*t]);
                acc[2*t+1] = ffma2(yy, wv.y, acc[2*t+1]);
            }
        }

        // ---- residual into the register-resident edge features ----
        #pragma unroll
        for (int t = 0; t < 16; t++) {
            float a, b; unpack2(acc[t], a, b);
            ewv[2*t] += a; ewv[2*t + 1] += b;
        }
    }

    if (valid) {
        float4* orow = (float4*)(out + eg * EDD);
        #pragma unroll
        for (int t = 0; t < 8; t++)
            orow[t] = make_float4(ewv[4*t], ewv[4*t+1], ewv[4*t+2], ewv[4*t+3]);
    }
}

static const int SMEM_BYTES =
    (TILE * XROWF + IND * EDD + EDD * EDD + 3 * EDD) * (int)sizeof(float)
    + 2 * TILE * (int)sizeof(int);   // = 93,568 B

extern "C" void kernel_launch(void* const* d_in, const int* in_sizes, int n_in,
                              void* d_out, int out_size) {
    const float* node_feat = (const float*)d_in[0];
    const float* edge_w    = (const float*)d_in[1];
    const float* ln_g      = (const float*)d_in[2];
    const float* ln_b      = (const float*)d_in[3];
    const float* w1        = (const float*)d_in[4];
    const float* b1        = (const float*)d_in[5];
    const float* w2        = (const float*)d_in[6];
    const float* b2        = (const float*)d_in[7];
    const int*   edge_i    = (const int*)d_in[8];
    const int*   edge_j    = (const int*)d_in[9];
    float* out = (float*)d_out;

    int E = in_sizes[8];

    prep_kernel<<<NLAYER, EDD>>>(ln_g, ln_b, w1, b1);

    cudaFuncSetAttribute(edge_kernel, cudaFuncAttributeMaxDynamicSharedMemorySize, SMEM_BYTES);
    int grid = (E + TILE - 1) / TILE;
    edge_kernel<<<grid, TILE, SMEM_BYTES>>>(node_feat, edge_w, w2, b2,
                                            edge_i, edge_j, out, E);
}

// round 5
// speedup vs baseline: 1.6607x; 1.6607x over previous
#include <cuda_runtime.h>
#include <cstdint>
#include <cstddef>

#define IND    160   // concat dim
#define EDD    32    // edge feature dim
#define NDD    64    // node feature dim
#define NLAYER 3
#define NMAX   100000
#define TILE   128   // threads per block
#define EPB    256   // edges per block (2 edges per thread)

typedef unsigned long long u64;

// ---- static device scratch (no allocation allowed) ----
__device__ float d_Wg[NLAYER * IND * EDD];            // g[k] * W1[k][c]
__device__ float d_S [NLAYER * EDD];                  // col-sums of Wg
__device__ float d_T [NLAYER * EDD];                  // b·W1 + b1
__device__ float d_P [(size_t)NLAYER * 2 * NMAX * EDD]; // per-node GEMM1 partials (76.8MB)
__device__ float d_sn[NMAX];                          // per-node sum of nf
__device__ float d_qn[NMAX];                          // per-node sum of nf^2

__device__ __forceinline__ u64 pack2(float lo, float hi) {
    u64 r; asm("mov.b64 %0,{%1,%2};" : "=l"(r) : "f"(lo), "f"(hi)); return r;
}
__device__ __forceinline__ void unpack2(u64 v, float& lo, float& hi) {
    asm("mov.b64 {%0,%1},%2;" : "=f"(lo), "=f"(hi) : "l"(v));
}
__device__ __forceinline__ u64 ffma2(u64 a, u64 b, u64 c) {
    u64 d; asm("fma.rn.f32x2 %0,%1,%2,%3;" : "=l"(d) : "l"(a), "l"(b), "l"(c)); return d;
}
__device__ __forceinline__ u64 add2(u64 a, u64 b) {
    u64 d; asm("add.rn.f32x2 %0,%1,%2;" : "=l"(d) : "l"(a), "l"(b)); return d;
}

// Fold LayerNorm affine into the first GEMM:
// y1[c] = rs*( dot(x, Wg[:,c]) - mu*S[c] ) + T[c]
__global__ void prep_kernel(const float* __restrict__ ln_g, const float* __restrict__ ln_b,
                            const float* __restrict__ w1,   const float* __restrict__ b1) {
    int l = blockIdx.x;   // 0..2
    int c = threadIdx.x;  // 0..31
    float s = 0.f, t = 0.f;
    for (int k = 0; k < IND; k++) {
        float wv = w1[(l * IND + k) * EDD + c];
        float wg = ln_g[l * IND + k] * wv;
        d_Wg[(l * IND + k) * EDD + c] = wg;
        s += wg;
        t = fmaf(ln_b[l * IND + k], wv, t);
    }
    d_S[l * EDD + c] = s;
    d_T[l * EDD + c] = t + b1[l * EDD + c];
}

// Per-node precompute: P[l][side][n][c] = sum_k nf[n][k] * Wg[l][side*64 + k][c]
// plus scalar LN-stat partials sn, qn.
__global__ void node_kernel(const float* __restrict__ nf, int N) {
    int n = blockIdx.x * blockDim.x + threadIdx.x;
    if (n >= N) return;

    float x[NDD];
    const float4* r = (const float4*)(nf + (size_t)n * NDD);
    #pragma unroll
    for (int t = 0; t < 16; t++) {
        float4 v = r[t];
        x[4*t] = v.x; x[4*t+1] = v.y; x[4*t+2] = v.z; x[4*t+3] = v.w;
    }
    float s = 0.f, q = 0.f;
    #pragma unroll
    for (int k = 0; k < NDD; k++) { s += x[k]; q = fmaf(x[k], x[k], q); }
    d_sn[n] = s;
    d_qn[n] = q;

    for (int ls = 0; ls < NLAYER * 2; ls++) {      // (l, side) pairs
        int l = ls >> 1, side = ls & 1;
        const float* W = d_Wg + (size_t)(l * IND + side * NDD) * EDD;
        u64 dot[16];
        #pragma unroll
        for (int t = 0; t < 16; t++) dot[t] = 0ull;
        #pragma unroll
        for (int k = 0; k < NDD; k++) {
            u64 xx = pack2(x[k], x[k]);
            const ulonglong2* wr = (const ulonglong2*)(W + k * EDD);
            #pragma unroll
            for (int t = 0; t < 8; t++) {
                ulonglong2 wv = wr[t];
                dot[2*t]   = ffma2(xx, wv.x, dot[2*t]);
                dot[2*t+1] = ffma2(xx, wv.y, dot[2*t+1]);
            }
        }
        u64* po = (u64*)(d_P + ((size_t)ls * N + n) * EDD);
        #pragma unroll
        for (int t = 0; t < 16; t++) po[t] = dot[t];
    }
}

__global__ void __launch_bounds__(TILE)
edge_kernel(const float* __restrict__ ew_g,
            const float* __restrict__ w2g, const float* __restrict__ b2g,
            const int* __restrict__ ei, const int* __restrict__ ej,
            float* __restrict__ out, int E, int N)
{
    __shared__ float wgE_s[EDD * EDD];   // Wg rows 128..159 (edge part of GEMM1)
    __shared__ float w2_s [EDD * EDD];
    __shared__ float S_s[EDD], T_s[EDD], b2_s[EDD];

    const int tid = threadIdx.x;
    const long long g0 = (long long)blockIdx.x * EPB + tid;
    const long long g1 = g0 + TILE;
    const bool v0 = (g0 < E), v1 = (g1 < E);
    const long long c0 = v0 ? g0 : 0, c1 = v1 ? g1 : 0;

    const int i0 = ei[c0], j0 = ej[c0];
    const int i1 = ei[c1], j1 = ej[c1];

    const float sb0 = d_sn[i0] + d_sn[j0];
    const float qb0 = d_qn[i0] + d_qn[j0];
    const float sb1 = d_sn[i1] + d_sn[j1];
    const float qb1 = d_qn[i1] + d_qn[j1];

    float eA[EDD], eB[EDD];
    {
        const float4* r0 = (const float4*)(ew_g + c0 * EDD);
        const float4* r1 = (const float4*)(ew_g + c1 * EDD);
        #pragma unroll
        for (int t = 0; t < 8; t++) {
            float4 a = r0[t], b = r1[t];
            eA[4*t] = a.x; eA[4*t+1] = a.y; eA[4*t+2] = a.z; eA[4*t+3] = a.w;
            eB[4*t] = b.x; eB[4*t+1] = b.y; eB[4*t+2] = b.z; eB[4*t+3] = b.w;
        }
    }

    for (int l = 0; l < NLAYER; l++) {
        __syncthreads();
        for (int t = tid; t < EDD * EDD; t += TILE) {
            wgE_s[t] = d_Wg[(size_t)(l * IND + (IND - EDD)) * EDD + t];
            w2_s[t]  = w2g[(size_t)l * EDD * EDD + t];
        }
        if (tid < EDD) {
            S_s[tid]  = d_S[l * EDD + tid];
            T_s[tid]  = d_T[l * EDD + tid];
            b2_s[tid] = b2g[l * EDD + tid];
        }
        __syncthreads();

        // ---- GEMM1: init from precomputed node partials, accumulate edge part ----
        u64 dA[16], dB[16];
        {
            const u64* paA = (const u64*)(d_P + ((size_t)(l * 2 + 0) * N + i0) * EDD);
            const u64* pbA = (const u64*)(d_P + ((size_t)(l * 2 + 1) * N + j0) * EDD);
            const u64* paB = (const u64*)(d_P + ((size_t)(l * 2 + 0) * N + i1) * EDD);
            const u64* pbB = (const u64*)(d_P + ((size_t)(l * 2 + 1) * N + j1) * EDD);
            #pragma unroll
            for (int t = 0; t < 16; t++) {
                dA[t] = add2(paA[t], pbA[t]);
                dB[t] = add2(paB[t], pbB[t]);
            }
        }
        float s0 = sb0, q0 = qb0, s1 = sb1, q1 = qb1;

        #pragma unroll
        for (int k = 0; k < EDD; k++) {
            float xa = eA[k], xb = eB[k];
            s0 += xa; q0 = fmaf(xa, xa, q0);
            s1 += xb; q1 = fmaf(xb, xb, q1);
            u64 XA = pack2(xa, xa), XB = pack2(xb, xb);
            const ulonglong2* wr = (const ulonglong2*)(wgE_s + k * EDD);
            #pragma unroll
            for (int t = 0; t < 8; t++) {
                ulonglong2 wv = wr[t];
                dA[2*t]   = ffma2(XA, wv.x, dA[2*t]);
                dA[2*t+1] = ffma2(XA, wv.y, dA[2*t+1]);
                dB[2*t]   = ffma2(XB, wv.x, dB[2*t]);
                dB[2*t+1] = ffma2(XB, wv.y, dB[2*t+1]);
            }
        }

        // ---- edge A: LN epilogue + LeakyReLU + GEMM2 + residual ----
        {
            float mu  = s0 * (1.f / IND);
            float var = q0 * (1.f / IND) - mu * mu;
            float rs  = rsqrtf(var + 1e-5f);
            float y1[EDD];
            #pragma unroll
            for (int t = 0; t < 16; t++) {
                float a, b; unpack2(dA[t], a, b);
                float u0 = fmaf(rs, a - mu * S_s[2*t],   T_s[2*t]);
                float u1 = fmaf(rs, b - mu * S_s[2*t+1], T_s[2*t+1]);
                y1[2*t]   = fmaxf(u0, 0.01f * u0);
                y1[2*t+1] = fmaxf(u1, 0.01f * u1);
            }
            u64 acc[16];
            {
                const ulonglong2* bp = (const ulonglong2*)b2_s;
                #pragma unroll
                for (int t = 0; t < 8; t++) { ulonglong2 v = bp[t]; acc[2*t] = v.x; acc[2*t+1] = v.y; }
            }
            #pragma unroll
            for (int k = 0; k < EDD; k++) {
                u64 yy = pack2(y1[k], y1[k]);
                const ulonglong2* wr = (const ulonglong2*)(w2_s + k * EDD);
                #pragma unroll
                for (int t = 0; t < 8; t++) {
                    ulonglong2 wv = wr[t];
                    acc[2*t]   = ffma2(yy, wv.x, acc[2*t]);
                    acc[2*t+1] = ffma2(yy, wv.y, acc[2*t+1]);
                }
            }
            #pragma unroll
            for (int t = 0; t < 16; t++) {
                float a, b; unpack2(acc[t], a, b);
                eA[2*t] += a; eA[2*t+1] += b;
            }
        }
        // ---- edge B ----
        {
            float mu  = s1 * (1.f / IND);
            float var = q1 * (1.f / IND) - mu * mu;
            float rs  = rsqrtf(var + 1e-5f);
            float y1[EDD];
            #pragma unroll
            for (int t = 0; t < 16; t++) {
                float a, b; unpack2(dB[t], a, b);
                float u0 = fmaf(rs, a - mu * S_s[2*t],   T_s[2*t]);
                float u1 = fmaf(rs, b - mu * S_s[2*t+1], T_s[2*t+1]);
                y1[2*t]   = fmaxf(u0, 0.01f * u0);
                y1[2*t+1] = fmaxf(u1, 0.01f * u1);
            }
            u64 acc[16];
            {
                const ulonglong2* bp = (const ulonglong2*)b2_s;
                #pragma unroll
                for (int t = 0; t < 8; t++) { ulonglong2 v = bp[t]; acc[2*t] = v.x; acc[2*t+1] = v.y; }
            }
            #pragma unroll
            for (int k = 0; k < EDD; k++) {
                u64 yy = pack2(y1[k], y1[k]);
                const ulonglong2* wr = (const ulonglong2*)(w2_s + k * EDD);
                #pragma unroll
                for (int t = 0; t < 8; t++) {
                    ulonglong2 wv = wr[t];
                    acc[2*t]   = ffma2(yy, wv.x, acc[2*t]);
                    acc[2*t+1] = ffma2(yy, wv.y, acc[2*t+1]);
                }
            }
            #pragma unroll
            for (int t = 0; t < 16; t++) {
                float a, b; unpack2(acc[t], a, b);
                eB[2*t] += a; eB[2*t+1] += b;
            }
        }
    }

    if (v0) {
        float4* o = (float4*)(out + g0 * EDD);
        #pragma unroll
        for (int t = 0; t < 8; t++)
            o[t] = make_float4(eA[4*t], eA[4*t+1], eA[4*t+2], eA[4*t+3]);
    }
    if (v1) {
        float4* o = (float4*)(out + g1 * EDD);
        #pragma unroll
        for (int t = 0; t < 8; t++)
            o[t] = make_float4(eB[4*t], eB[4*t+1], eB[4*t+2], eB[4*t+3]);
    }
}

extern "C" void kernel_launch(void* const* d_in, const int* in_sizes, int n_in,
                              void* d_out, int out_size) {
    const float* node_feat = (const float*)d_in[0];
    const float* edge_w    = (const float*)d_in[1];
    const float* ln_g      = (const float*)d_in[2];
    const float* ln_b      = (const float*)d_in[3];
    const float* w1        = (const float*)d_in[4];
    const float* b1        = (const float*)d_in[5];
    const float* w2        = (const float*)d_in[6];
    const float* b2        = (const float*)d_in[7];
    const int*   edge_i    = (const int*)d_in[8];
    const int*   edge_j    = (const int*)d_in[9];
    float* out = (float*)d_out;

    int E = in_sizes[8];
    int N = in_sizes[0] / NDD;
    if (N > NMAX) N = NMAX;

    prep_kernel<<<NLAYER, EDD>>>(ln_g, ln_b, w1, b1);
    node_kernel<<<(N + TILE - 1) / TILE, TILE>>>(node_feat, N);

    int grid = (E + EPB - 1) / EPB;
    edge_kernel<<<grid, TILE>>>(edge_w, w2, b2, edge_i, edge_j, out, E, N);
}